// round 12
// baseline (speedup 1.0000x reference)
#include <cuda_runtime.h>
#include <cuda_fp16.h>
#include <cstdint>
#include <cstddef>

// ---------------------------------------------------------------------------
// GCN 2-layer forward on GB300 — fp16 HMMA GEMMs + gather SpMM.
//   h1 = x @ W1           (fp16 HMMA, BM=64, 3 CTAs/SM)   [k_hgemm1]
//   a1 = relu(Ahat h1+b1) (fp16-stored)                   [k_spmm1]
//   h2 = a1 @ W2          (fp16 HMMA, fp16 A path)        [k_hgemm2]
//   out = Ahat h2 + b2    (fp32 out)                      [k_spmm2]
// R12: GEMM1 tiled BM=64 -> ~70 regs -> 3 CTAs/SM (was 2) to hide DRAM
// latency; init_deg merged into wcvt.
// ---------------------------------------------------------------------------

#define NNODES 100000
#define NEDGES 1600000
#define NNZ    (NNODES + NEDGES)

__device__ int   g_deg[NNODES];
__device__ int   g_fill[NNODES];
__device__ int   g_rowstart[NNODES + 1];
__device__ int   g_bsums[256];
__device__ float g_dinv[NNODES];
__device__ int   g_col[NNZ];
__device__ float g_wgt[NNZ];
__device__ __half g_h1[(size_t)NNODES * 128];   // h1 (fp16)
__device__ __half g_a1[(size_t)NNODES * 128];   // a1 (fp16)
__device__ __half g_h2[(size_t)NNODES * 64];    // h2 (fp16)
// W transposed K-major [N][K], fp16
__device__ __half g_w1[128 * 256];
__device__ __half g_w2[64 * 128];

// ------------------------------ helpers ------------------------------------

__device__ __forceinline__ uint32_t smem_u32(const void* p) {
    uint32_t a;
    asm("{ .reg .u64 t; cvta.to.shared.u64 t, %1; cvt.u32.u64 %0, t; }"
        : "=r"(a) : "l"(p));
    return a;
}

#define LDMATRIX_X4(r, addr) \
    asm volatile("ldmatrix.sync.aligned.m8n8.x4.shared.b16 {%0,%1,%2,%3}, [%4];" \
                 : "=r"((r)[0]), "=r"((r)[1]), "=r"((r)[2]), "=r"((r)[3]) \
                 : "r"(addr))

#define MMA_F16(c, a, b0, b1) \
    asm volatile( \
        "mma.sync.aligned.m16n8k16.row.col.f32.f16.f16.f32 " \
        "{%0,%1,%2,%3}, {%4,%5,%6,%7}, {%8,%9}, {%0,%1,%2,%3};" \
        : "+f"((c)[0]), "+f"((c)[1]), "+f"((c)[2]), "+f"((c)[3]) \
        : "r"((a)[0]), "r"((a)[1]), "r"((a)[2]), "r"((a)[3]), \
          "r"(b0), "r"(b1))

// ldmatrix x4 address, 64B-row buffer: swizzle kg ^= (row>>1)&3
__device__ __forceinline__ uint32_t lm_addr64(uint32_t buf, int rowbase, int ks,
                                              int lane) {
    int row = rowbase + (lane & 15);
    int kg = ks * 2 + (lane >> 4);
    return buf + row * 64 + (((kg ^ ((row >> 1) & 3))) << 4);
}

// ---------------------------------------------------------------------------
// CSR construction
// ---------------------------------------------------------------------------

// W convert (both layers) + deg init, one launch
__global__ void k_wcvt_init(const float* __restrict__ W1,
                            const float* __restrict__ W2, int n) {
    int idx = blockIdx.x * blockDim.x + threadIdx.x;
    if (idx < 128 * 256) {                 // W1: K=256, N=128
        int nn = idx / 256, k = idx % 256;
        g_w1[idx] = __float2half_rn(W1[k * 128 + nn]);
    } else if (idx < 128 * 256 + 64 * 128) {  // W2: K=128, N=64
        int j = idx - 128 * 256;
        int nn = j / 128, k = j % 128;
        g_w2[j] = __float2half_rn(W2[k * 64 + nn]);
    }
    if (idx < n) g_deg[idx] = 1;           // self loop
}

__global__ void k_count(const int* __restrict__ dst, int e) {
    int i = blockIdx.x * blockDim.x + threadIdx.x;
    if (i < e) atomicAdd(&g_deg[dst[i]], 1);
}

__global__ void k_scan1(int n) {
    __shared__ int s[1024];
    int gid = blockIdx.x * 1024 + threadIdx.x;
    int v = (gid < n) ? g_deg[gid] : 0;
    s[threadIdx.x] = v;
    __syncthreads();
    for (int off = 1; off < 1024; off <<= 1) {
        int t = (threadIdx.x >= off) ? s[threadIdx.x - off] : 0;
        __syncthreads();
        s[threadIdx.x] += t;
        __syncthreads();
    }
    if (gid < n) g_rowstart[gid] = s[threadIdx.x] - v;
    if (threadIdx.x == 1023) g_bsums[blockIdx.x] = s[1023];
}

__global__ void k_scanfill(int n, int nb) {
    __shared__ int soff;
    int gid = blockIdx.x * 1024 + threadIdx.x;
    if (threadIdx.x == 0) {
        int o = 0;
        for (int b = 0; b < (int)blockIdx.x; b++) o += g_bsums[b];
        soff = o;
    }
    __syncthreads();
    if (gid < n) {
        int rs = g_rowstart[gid] + soff;
        g_rowstart[gid] = rs;
        float d = rsqrtf((float)g_deg[gid]);
        g_dinv[gid] = d;
        g_col[rs] = gid;
        g_wgt[rs] = d * d;
        g_fill[gid] = 1;
    }
    if (gid == 0) {
        int o = 0;
        for (int b = 0; b < nb; b++) o += g_bsums[b];
        g_rowstart[n] = o;
    }
}

__global__ void k_fill_edges(const int* __restrict__ src,
                             const int* __restrict__ dst, int e) {
    int i = blockIdx.x * blockDim.x + threadIdx.x;
    if (i < e) {
        int s = src[i];
        int d = dst[i];
        int p = g_rowstart[d] + atomicAdd(&g_fill[d], 1);
        g_col[p] = s;
        g_wgt[p] = g_dinv[s] * g_dinv[d];
    }
}

// ---------------------------------------------------------------------------
// GEMM1: h1[M,128] = x[M,256](fp32) @ W1, fp16 HMMA.
// BM=64, 8 warps as 2(m)x4(n), reg double-buffered, 3 CTAs/SM.
// ---------------------------------------------------------------------------

__global__ void __launch_bounds__(256, 3) k_hgemm1(const float* __restrict__ A,
                                                   int M) {
    constexpr int N_ = 128, K_ = 256;
    constexpr int NCHUNK = K_ / 32;      // 8
    constexpr int OFF_B = 4096;          // A tile: 64 rows x 64B = 4KB

    __shared__ __align__(128) char smem[4096 + N_ * 64];   // 4KB + 8KB

    const __half* __restrict__ Bw = g_w1;
    const uint32_t sb = smem_u32(smem);
    const int tid = threadIdx.x;
    const int wid = tid >> 5, lane = tid & 31;
    const int wm = wid & 1, wn = wid >> 1;   // 2(m) x 4(n)
    const int m0 = blockIdx.x * 64;

    float acc[2][4][4];                  // 2 mtiles x 4 n8tiles x 4
#pragma unroll
    for (int i = 0; i < 2; i++)
#pragma unroll
        for (int j = 0; j < 4; j++)
#pragma unroll
            for (int q = 0; q < 4; q++) acc[i][j][q] = 0.f;

    // A stage: 64 rows x 8 float4 = 512 -> 2 per thread
    const int a_row[2] = {tid >> 3, (tid + 256) >> 3};
    const int a_f4 = tid & 7;

    float4 pa[2];
    uint4 pb[2];                          // B: 128 rows x 2 uint4 = 512 -> 2/thread
#pragma unroll
    for (int i = 0; i < 2; i++) {
        int gr = m0 + a_row[i];
        pa[i] = make_float4(0.f, 0.f, 0.f, 0.f);
        if (gr < M) pa[i] = *(const float4*)(A + (size_t)gr * K_ + a_f4 * 4);
    }
#pragma unroll
    for (int i = 0; i < 2; i++) {
        int idx = tid + i * 256;
        int row = idx >> 2, kg = idx & 3;
        pb[i] = *(const uint4*)(Bw + (size_t)row * K_ + kg * 8);
    }

    for (int chunk = 0; chunk < NCHUNK; chunk++) {
#pragma unroll
        for (int i = 0; i < 2; i++) {
            float4 v = pa[i];
            int row = a_row[i];
            __half2 p0 = __floats2half2_rn(v.x, v.y);
            __half2 p1 = __floats2half2_rn(v.z, v.w);
            int kg = a_f4 >> 1, half = a_f4 & 1;
            uint32_t byte = row * 64 + ((kg ^ ((row >> 1) & 3)) << 4) + half * 8;
            *(uint2*)(smem + byte) = make_uint2(*(uint32_t*)&p0, *(uint32_t*)&p1);
        }
#pragma unroll
        for (int i = 0; i < 2; i++) {
            int idx = tid + i * 256;
            int row = idx >> 2, kg = idx & 3;
            uint32_t byte = row * 64 + ((kg ^ ((row >> 1) & 3)) << 4);
            *(uint4*)(smem + OFF_B + byte) = pb[i];
        }
        __syncthreads();

        if (chunk + 1 < NCHUNK) {
            const int k0 = (chunk + 1) * 32;
#pragma unroll
            for (int i = 0; i < 2; i++) {
                int gr = m0 + a_row[i];
                pa[i] = make_float4(0.f, 0.f, 0.f, 0.f);
                if (gr < M)
                    pa[i] = *(const float4*)(A + (size_t)gr * K_ + k0 + a_f4 * 4);
            }
#pragma unroll
            for (int i = 0; i < 2; i++) {
                int idx = tid + i * 256;
                int row = idx >> 2, kg = idx & 3;
                pb[i] = *(const uint4*)(Bw + (size_t)row * K_ + k0 + kg * 8);
            }
        }

#pragma unroll
        for (int ks = 0; ks < 2; ks++) {
            uint32_t am[2][4];
#pragma unroll
            for (int mt = 0; mt < 2; mt++) {
                LDMATRIX_X4(am[mt], lm_addr64(sb, wm * 32 + mt * 16, ks, lane));
            }
#pragma unroll
            for (int nt = 0; nt < 2; nt++) {   // 2 x 16-wide n tiles (32 cols)
                uint32_t bm[4];
                LDMATRIX_X4(bm, lm_addr64(sb + OFF_B, wn * 32 + nt * 16, ks, lane));
#pragma unroll
                for (int mt = 0; mt < 2; mt++) {
                    MMA_F16(acc[mt][nt * 2 + 0], am[mt], bm[0], bm[2]);
                    MMA_F16(acc[mt][nt * 2 + 1], am[mt], bm[1], bm[3]);
                }
            }
        }
        __syncthreads();
    }

#pragma unroll
    for (int mt = 0; mt < 2; mt++) {
#pragma unroll
        for (int nt8 = 0; nt8 < 4; nt8++) {
            const float* c = acc[mt][nt8];
            int row0 = m0 + wm * 32 + mt * 16 + (lane >> 2);
            int col = wn * 32 + nt8 * 8 + 2 * (lane & 3);
            __half2 p0 = __floats2half2_rn(c[0], c[1]);
            __half2 p1 = __floats2half2_rn(c[2], c[3]);
            if (row0 < M)
                *(uint32_t*)(g_h1 + (size_t)row0 * N_ + col) = *(uint32_t*)&p0;
            if (row0 + 8 < M)
                *(uint32_t*)(g_h1 + (size_t)(row0 + 8) * N_ + col) = *(uint32_t*)&p1;
        }
    }
}

// ---------------------------------------------------------------------------
// GEMM2: h2[M,64] = a1[M,128](fp16) @ W2, fp16 A path.
// ---------------------------------------------------------------------------

__global__ void __launch_bounds__(256, 2) k_hgemm2(int M) {
    constexpr int N_ = 64, K_ = 128;
    constexpr int NCHUNK = K_ / 32;      // 4
    constexpr int NT16 = N_ / 32;        // 2
    constexpr int OFF_B = 8192;

    __shared__ __align__(128) char smem[8192 + N_ * 64];

    const __half* __restrict__ A = g_a1;
    const __half* __restrict__ Bw = g_w2;
    const uint32_t sb = smem_u32(smem);
    const int tid = threadIdx.x;
    const int wid = tid >> 5, lane = tid & 31;
    const int wm = wid & 3, wn = wid >> 2;
    const int m0 = blockIdx.x * 128;

    float acc[2][N_ / 16][4];
#pragma unroll
    for (int i = 0; i < 2; i++)
#pragma unroll
        for (int j = 0; j < N_ / 16; j++)
#pragma unroll
            for (int q = 0; q < 4; q++) acc[i][j][q] = 0.f;

    const int a_row[2] = {tid >> 2, (tid + 256) >> 2};
    const int a_kg = tid & 3;

    uint4 pa[2];
    uint4 pb;
#pragma unroll
    for (int i = 0; i < 2; i++) {
        int gr = m0 + a_row[i];
        pa[i] = make_uint4(0u, 0u, 0u, 0u);
        if (gr < M) pa[i] = *(const uint4*)(A + (size_t)gr * K_ + a_kg * 8);
    }
    {
        int row = tid >> 2, kg = tid & 3;
        pb = *(const uint4*)(Bw + (size_t)row * K_ + kg * 8);
    }

    for (int chunk = 0; chunk < NCHUNK; chunk++) {
#pragma unroll
        for (int i = 0; i < 2; i++) {
            int row = a_row[i];
            uint32_t byte = row * 64 + ((a_kg ^ ((row >> 1) & 3)) << 4);
            *(uint4*)(smem + byte) = pa[i];
        }
        {
            int row = tid >> 2, kg = tid & 3;
            uint32_t byte = row * 64 + ((kg ^ ((row >> 1) & 3)) << 4);
            *(uint4*)(smem + OFF_B + byte) = pb;
        }
        __syncthreads();

        if (chunk + 1 < NCHUNK) {
            const int k0 = (chunk + 1) * 32;
#pragma unroll
            for (int i = 0; i < 2; i++) {
                int gr = m0 + a_row[i];
                pa[i] = make_uint4(0u, 0u, 0u, 0u);
                if (gr < M)
                    pa[i] = *(const uint4*)(A + (size_t)gr * K_ + k0 + a_kg * 8);
            }
            int row = tid >> 2, kg = tid & 3;
            pb = *(const uint4*)(Bw + (size_t)row * K_ + k0 + kg * 8);
        }

#pragma unroll
        for (int ks = 0; ks < 2; ks++) {
            uint32_t am[2][4];
#pragma unroll
            for (int mt = 0; mt < 2; mt++) {
                LDMATRIX_X4(am[mt], lm_addr64(sb, wm * 32 + mt * 16, ks, lane));
            }
#pragma unroll
            for (int nt = 0; nt < NT16; nt++) {
                uint32_t bm[4];
                LDMATRIX_X4(bm, lm_addr64(sb + OFF_B, wn * (N_ / 2) + nt * 16,
                                          ks, lane));
#pragma unroll
                for (int mt = 0; mt < 2; mt++) {
                    MMA_F16(acc[mt][nt * 2 + 0], am[mt], bm[0], bm[2]);
                    MMA_F16(acc[mt][nt * 2 + 1], am[mt], bm[1], bm[3]);
                }
            }
        }
        __syncthreads();
    }

#pragma unroll
    for (int mt = 0; mt < 2; mt++) {
#pragma unroll
        for (int nt8 = 0; nt8 < N_ / 16; nt8++) {
            const float* c = acc[mt][nt8];
            int row0 = m0 + wm * 32 + mt * 16 + (lane >> 2);
            int col = wn * (N_ / 2) + nt8 * 8 + 2 * (lane & 3);
            __half2 p0 = __floats2half2_rn(c[0], c[1]);
            __half2 p1 = __floats2half2_rn(c[2], c[3]);
            if (row0 < M)
                *(uint32_t*)(g_h2 + (size_t)row0 * N_ + col) = *(uint32_t*)&p0;
            if (row0 + 8 < M)
                *(uint32_t*)(g_h2 + (size_t)(row0 + 8) * N_ + col) = *(uint32_t*)&p1;
        }
    }
}

// ---------------------------------------------------------------------------
// SpMM layer 1: a1 = relu(Ahat @ h1(fp16) + b1), fp16-stored. warp/node.
// ---------------------------------------------------------------------------

__launch_bounds__(256)
__global__ void k_spmm1(const float* __restrict__ bias, int n) {
    int w = (blockIdx.x * 256 + threadIdx.x) >> 5;
    int lane = threadIdx.x & 31;
    if (w >= n) return;
    int beg = g_rowstart[w], end = g_rowstart[w + 1];

    float4 acc = make_float4(0.f, 0.f, 0.f, 0.f);
    const __half* hb = g_h1 + lane * 4;
    for (int e = beg; e < end; e++) {
        int s = g_col[e];
        float wt = g_wgt[e];
        uint2 raw = *(const uint2*)(hb + (size_t)s * 128);
        float2 f01 = __half22float2(*reinterpret_cast<__half2*>(&raw.x));
        float2 f23 = __half22float2(*reinterpret_cast<__half2*>(&raw.y));
        acc.x += wt * f01.x; acc.y += wt * f01.y;
        acc.z += wt * f23.x; acc.w += wt * f23.y;
    }
    float4 b = *(const float4*)(bias + lane * 4);
    __half2 p0 = __floats2half2_rn(fmaxf(acc.x + b.x, 0.f),
                                   fmaxf(acc.y + b.y, 0.f));
    __half2 p1 = __floats2half2_rn(fmaxf(acc.z + b.z, 0.f),
                                   fmaxf(acc.w + b.w, 0.f));
    *(uint2*)(g_a1 + (size_t)w * 128 + lane * 4) =
        make_uint2(*(uint32_t*)&p0, *(uint32_t*)&p1);
}

// ---------------------------------------------------------------------------
// SpMM layer 2: out = Ahat @ h2(fp16) + b2, F=64.
// ---------------------------------------------------------------------------

__launch_bounds__(256)
__global__ void k_spmm2(const float* __restrict__ bias, float* __restrict__ out,
                        int n) {
    int w = (blockIdx.x * 256 + threadIdx.x) >> 5;
    int lane = threadIdx.x & 31;
    if (w >= n) return;
    int beg = g_rowstart[w], end = g_rowstart[w + 1];

    float2 acc = make_float2(0.f, 0.f);
    const __half* hb = g_h2 + lane * 2;
    for (int e = beg; e < end; e++) {
        int s = g_col[e];
        float wt = g_wgt[e];
        uint32_t raw = *(const uint32_t*)(hb + (size_t)s * 64);
        float2 v = __half22float2(*reinterpret_cast<__half2*>(&raw));
        acc.x += wt * v.x; acc.y += wt * v.y;
    }
    float2 b = *(const float2*)(bias + lane * 2);
    acc.x += b.x; acc.y += b.y;
    *(float2*)(out + (size_t)w * 64 + lane * 2) = acc;
}

// ---------------------------------------------------------------------------

extern "C" void kernel_launch(void* const* d_in, const int* in_sizes, int n_in,
                              void* d_out, int out_size) {
    const float* x = (const float*)d_in[0];
    const int* ei = (const int*)d_in[1];      // int32
    const float* W1 = (const float*)d_in[2];
    const float* b1 = (const float*)d_in[3];
    const float* W2 = (const float*)d_in[4];
    const float* b2 = (const float*)d_in[5];
    float* out = (float*)d_out;

    const int N = in_sizes[0] / 256;   // 100000
    const int E = in_sizes[1] / 2;     // 1600000
    const int* src = ei;
    const int* dst = ei + E;
    const int NB = (N + 1023) / 1024;

    // #1..#3
    k_wcvt_init<<<(N + 255) / 256, 256>>>(W1, W2, N);
    k_count<<<(E + 255) / 256, 256>>>(dst, E);
    k_scan1<<<NB, 1024>>>(N);

    // #4: GEMM1 — ncu capture lands here
    k_hgemm1<<<(N + 63) / 64, 256>>>(x, N);

    // #5..#6: CSR finish
    k_scanfill<<<NB, 1024>>>(N, NB);
    k_fill_edges<<<(E + 255) / 256, 256>>>(src, dst, E);

    // #7: a1 = relu(Ahat h1 + b1), fp16
    k_spmm1<<<((N * 32) + 255) / 256, 256>>>(b1, N);

    // #8: h2 = a1 @ W2
    k_hgemm2<<<(N + 127) / 128, 256>>>(N);

    // #9: out = Ahat h2 + b2
    k_spmm2<<<((N * 32) + 255) / 256, 256>>>(b2, out, N);
}

// round 13
// speedup vs baseline: 1.0446x; 1.0446x over previous
#include <cuda_runtime.h>
#include <cuda_fp16.h>
#include <cstdint>
#include <cstddef>

// ---------------------------------------------------------------------------
// GCN 2-layer forward on GB300 — fp16 HMMA GEMMs + gather SpMM.
//   h1 = x @ W1           (fp16 HMMA, BM=128 — R11 config) [k_hgemm1]
//   a1 = relu(Ahat h1+b1) (fp16-stored)                    [k_spmm1]
//   h2 = a1 @ W2          (fp16 HMMA, fp16 A path)         [k_hgemm2]
//   out = Ahat h2 + b2    (fp32 out)                       [k_spmm2]
// R13: GEMM1 reverted to BM=128 (R12's BM=64 doubled B traffic);
// (col,wgt) packed into one 8-byte record -> one store per edge in
// fill_edges, one LDG.64 per edge in the SpMM loops.
// ---------------------------------------------------------------------------

#define NNODES 100000
#define NEDGES 1600000
#define NNZ    (NNODES + NEDGES)

__device__ int   g_deg[NNODES];
__device__ int   g_fill[NNODES];
__device__ int   g_rowstart[NNODES + 1];
__device__ int   g_bsums[256];
__device__ float g_dinv[NNODES];
__device__ int2  g_cw[NNZ];                     // .x = col, .y = wgt bits
__device__ __half g_h1[(size_t)NNODES * 128];   // h1 (fp16)
__device__ __half g_a1[(size_t)NNODES * 128];   // a1 (fp16)
__device__ __half g_h2[(size_t)NNODES * 64];    // h2 (fp16)
// W transposed K-major [N][K], fp16
__device__ __half g_w1[128 * 256];
__device__ __half g_w2[64 * 128];

// ------------------------------ helpers ------------------------------------

__device__ __forceinline__ uint32_t smem_u32(const void* p) {
    uint32_t a;
    asm("{ .reg .u64 t; cvta.to.shared.u64 t, %1; cvt.u32.u64 %0, t; }"
        : "=r"(a) : "l"(p));
    return a;
}

#define LDMATRIX_X4(r, addr) \
    asm volatile("ldmatrix.sync.aligned.m8n8.x4.shared.b16 {%0,%1,%2,%3}, [%4];" \
                 : "=r"((r)[0]), "=r"((r)[1]), "=r"((r)[2]), "=r"((r)[3]) \
                 : "r"(addr))

#define MMA_F16(c, a, b0, b1) \
    asm volatile( \
        "mma.sync.aligned.m16n8k16.row.col.f32.f16.f16.f32 " \
        "{%0,%1,%2,%3}, {%4,%5,%6,%7}, {%8,%9}, {%0,%1,%2,%3};" \
        : "+f"((c)[0]), "+f"((c)[1]), "+f"((c)[2]), "+f"((c)[3]) \
        : "r"((a)[0]), "r"((a)[1]), "r"((a)[2]), "r"((a)[3]), \
          "r"(b0), "r"(b1))

// ldmatrix x4 address, 64B-row buffer: swizzle kg ^= (row>>1)&3
__device__ __forceinline__ uint32_t lm_addr64(uint32_t buf, int rowbase, int ks,
                                              int lane) {
    int row = rowbase + (lane & 15);
    int kg = ks * 2 + (lane >> 4);
    return buf + row * 64 + (((kg ^ ((row >> 1) & 3))) << 4);
}

// ---------------------------------------------------------------------------
// CSR construction
// ---------------------------------------------------------------------------

// W convert (both layers) + deg init, one launch
__global__ void k_wcvt_init(const float* __restrict__ W1,
                            const float* __restrict__ W2, int n) {
    int idx = blockIdx.x * blockDim.x + threadIdx.x;
    if (idx < 128 * 256) {                 // W1: K=256, N=128
        int nn = idx / 256, k = idx % 256;
        g_w1[idx] = __float2half_rn(W1[k * 128 + nn]);
    } else if (idx < 128 * 256 + 64 * 128) {  // W2: K=128, N=64
        int j = idx - 128 * 256;
        int nn = j / 128, k = j % 128;
        g_w2[j] = __float2half_rn(W2[k * 64 + nn]);
    }
    if (idx < n) g_deg[idx] = 1;           // self loop
}

__global__ void k_count(const int* __restrict__ dst, int e) {
    int i = blockIdx.x * blockDim.x + threadIdx.x;
    if (i < e) atomicAdd(&g_deg[dst[i]], 1);
}

__global__ void k_scan1(int n) {
    __shared__ int s[1024];
    int gid = blockIdx.x * 1024 + threadIdx.x;
    int v = (gid < n) ? g_deg[gid] : 0;
    s[threadIdx.x] = v;
    __syncthreads();
    for (int off = 1; off < 1024; off <<= 1) {
        int t = (threadIdx.x >= off) ? s[threadIdx.x - off] : 0;
        __syncthreads();
        s[threadIdx.x] += t;
        __syncthreads();
    }
    if (gid < n) g_rowstart[gid] = s[threadIdx.x] - v;
    if (threadIdx.x == 1023) g_bsums[blockIdx.x] = s[1023];
}

__global__ void k_scanfill(int n, int nb) {
    __shared__ int soff;
    int gid = blockIdx.x * 1024 + threadIdx.x;
    if (threadIdx.x == 0) {
        int o = 0;
        for (int b = 0; b < (int)blockIdx.x; b++) o += g_bsums[b];
        soff = o;
    }
    __syncthreads();
    if (gid < n) {
        int rs = g_rowstart[gid] + soff;
        g_rowstart[gid] = rs;
        float d = rsqrtf((float)g_deg[gid]);
        g_dinv[gid] = d;
        g_cw[rs] = make_int2(gid, __float_as_int(d * d));
        g_fill[gid] = 1;
    }
    if (gid == 0) {
        int o = 0;
        for (int b = 0; b < nb; b++) o += g_bsums[b];
        g_rowstart[n] = o;
    }
}

__global__ void k_fill_edges(const int* __restrict__ src,
                             const int* __restrict__ dst, int e) {
    int i = blockIdx.x * blockDim.x + threadIdx.x;
    if (i < e) {
        int s = src[i];
        int d = dst[i];
        int p = g_rowstart[d] + atomicAdd(&g_fill[d], 1);
        g_cw[p] = make_int2(s, __float_as_int(g_dinv[s] * g_dinv[d]));
    }
}

// ---------------------------------------------------------------------------
// GEMM1: h1[M,128] = x[M,256](fp32) @ W1, fp16 HMMA, BM=128, reg dbuf.
// ---------------------------------------------------------------------------

__global__ void __launch_bounds__(256, 2) k_hgemm1(const float* __restrict__ A,
                                                   int M) {
    constexpr int N_ = 128, K_ = 256;
    constexpr int NCHUNK = K_ / 32;
    constexpr int NT16 = N_ / 32;
    constexpr int NBQ = 2;
    constexpr int OFF_B = 8192;

    __shared__ __align__(128) char smem[8192 + N_ * 64];

    const __half* __restrict__ Bw = g_w1;
    const uint32_t sb = smem_u32(smem);
    const int tid = threadIdx.x;
    const int wid = tid >> 5, lane = tid & 31;
    const int wm = wid & 3, wn = wid >> 2;
    const int m0 = blockIdx.x * 128;

    float acc[2][N_ / 16][4];
#pragma unroll
    for (int i = 0; i < 2; i++)
#pragma unroll
        for (int j = 0; j < N_ / 16; j++)
#pragma unroll
            for (int q = 0; q < 4; q++) acc[i][j][q] = 0.f;

    const int a_row[4] = {tid >> 3, (tid + 256) >> 3, (tid + 512) >> 3,
                          (tid + 768) >> 3};
    const int a_f4 = tid & 7;

    float4 pa[4];
    uint4 pb[NBQ];
#pragma unroll
    for (int i = 0; i < 4; i++) {
        int gr = m0 + a_row[i];
        pa[i] = make_float4(0.f, 0.f, 0.f, 0.f);
        if (gr < M) pa[i] = *(const float4*)(A + (size_t)gr * K_ + a_f4 * 4);
    }
#pragma unroll
    for (int i = 0; i < NBQ; i++) {
        int idx = tid + i * 256;
        int row = idx >> 2, kg = idx & 3;
        pb[i] = *(const uint4*)(Bw + (size_t)row * K_ + kg * 8);
    }

    for (int chunk = 0; chunk < NCHUNK; chunk++) {
#pragma unroll
        for (int i = 0; i < 4; i++) {
            float4 v = pa[i];
            int row = a_row[i];
            __half2 p0 = __floats2half2_rn(v.x, v.y);
            __half2 p1 = __floats2half2_rn(v.z, v.w);
            int kg = a_f4 >> 1, half = a_f4 & 1;
            uint32_t byte = row * 64 + ((kg ^ ((row >> 1) & 3)) << 4) + half * 8;
            *(uint2*)(smem + byte) = make_uint2(*(uint32_t*)&p0, *(uint32_t*)&p1);
        }
#pragma unroll
        for (int i = 0; i < NBQ; i++) {
            int idx = tid + i * 256;
            int row = idx >> 2, kg = idx & 3;
            uint32_t byte = row * 64 + ((kg ^ ((row >> 1) & 3)) << 4);
            *(uint4*)(smem + OFF_B + byte) = pb[i];
        }
        __syncthreads();

        if (chunk + 1 < NCHUNK) {
            const int k0 = (chunk + 1) * 32;
#pragma unroll
            for (int i = 0; i < 4; i++) {
                int gr = m0 + a_row[i];
                pa[i] = make_float4(0.f, 0.f, 0.f, 0.f);
                if (gr < M)
                    pa[i] = *(const float4*)(A + (size_t)gr * K_ + k0 + a_f4 * 4);
            }
#pragma unroll
            for (int i = 0; i < NBQ; i++) {
                int idx = tid + i * 256;
                int row = idx >> 2, kg = idx & 3;
                pb[i] = *(const uint4*)(Bw + (size_t)row * K_ + k0 + kg * 8);
            }
        }

#pragma unroll
        for (int ks = 0; ks < 2; ks++) {
            uint32_t am[2][4];
#pragma unroll
            for (int mt = 0; mt < 2; mt++) {
                LDMATRIX_X4(am[mt], lm_addr64(sb, wm * 32 + mt * 16, ks, lane));
            }
#pragma unroll
            for (int nt = 0; nt < NT16; nt++) {
                uint32_t bm[4];
                LDMATRIX_X4(bm, lm_addr64(sb + OFF_B, wn * (N_ / 2) + nt * 16,
                                          ks, lane));
#pragma unroll
                for (int mt = 0; mt < 2; mt++) {
                    MMA_F16(acc[mt][nt * 2 + 0], am[mt], bm[0], bm[2]);
                    MMA_F16(acc[mt][nt * 2 + 1], am[mt], bm[1], bm[3]);
                }
            }
        }
        __syncthreads();
    }

#pragma unroll
    for (int mt = 0; mt < 2; mt++) {
#pragma unroll
        for (int nt8 = 0; nt8 < N_ / 16; nt8++) {
            const float* c = acc[mt][nt8];
            int row0 = m0 + wm * 32 + mt * 16 + (lane >> 2);
            int col = wn * (N_ / 2) + nt8 * 8 + 2 * (lane & 3);
            __half2 p0 = __floats2half2_rn(c[0], c[1]);
            __half2 p1 = __floats2half2_rn(c[2], c[3]);
            if (row0 < M)
                *(uint32_t*)(g_h1 + (size_t)row0 * N_ + col) = *(uint32_t*)&p0;
            if (row0 + 8 < M)
                *(uint32_t*)(g_h1 + (size_t)(row0 + 8) * N_ + col) = *(uint32_t*)&p1;
        }
    }
}

// ---------------------------------------------------------------------------
// GEMM2: h2[M,64] = a1[M,128](fp16) @ W2, fp16 A path.
// ---------------------------------------------------------------------------

__global__ void __launch_bounds__(256, 2) k_hgemm2(int M) {
    constexpr int N_ = 64, K_ = 128;
    constexpr int NCHUNK = K_ / 32;      // 4
    constexpr int NT16 = N_ / 32;        // 2
    constexpr int OFF_B = 8192;

    __shared__ __align__(128) char smem[8192 + N_ * 64];

    const __half* __restrict__ A = g_a1;
    const __half* __restrict__ Bw = g_w2;
    const uint32_t sb = smem_u32(smem);
    const int tid = threadIdx.x;
    const int wid = tid >> 5, lane = tid & 31;
    const int wm = wid & 3, wn = wid >> 2;
    const int m0 = blockIdx.x * 128;

    float acc[2][N_ / 16][4];
#pragma unroll
    for (int i = 0; i < 2; i++)
#pragma unroll
        for (int j = 0; j < N_ / 16; j++)
#pragma unroll
            for (int q = 0; q < 4; q++) acc[i][j][q] = 0.f;

    const int a_row[2] = {tid >> 2, (tid + 256) >> 2};
    const int a_kg = tid & 3;

    uint4 pa[2];
    uint4 pb;
#pragma unroll
    for (int i = 0; i < 2; i++) {
        int gr = m0 + a_row[i];
        pa[i] = make_uint4(0u, 0u, 0u, 0u);
        if (gr < M) pa[i] = *(const uint4*)(A + (size_t)gr * K_ + a_kg * 8);
    }
    {
        int row = tid >> 2, kg = tid & 3;
        pb = *(const uint4*)(Bw + (size_t)row * K_ + kg * 8);
    }

    for (int chunk = 0; chunk < NCHUNK; chunk++) {
#pragma unroll
        for (int i = 0; i < 2; i++) {
            int row = a_row[i];
            uint32_t byte = row * 64 + ((a_kg ^ ((row >> 1) & 3)) << 4);
            *(uint4*)(smem + byte) = pa[i];
        }
        {
            int row = tid >> 2, kg = tid & 3;
            uint32_t byte = row * 64 + ((kg ^ ((row >> 1) & 3)) << 4);
            *(uint4*)(smem + OFF_B + byte) = pb;
        }
        __syncthreads();

        if (chunk + 1 < NCHUNK) {
            const int k0 = (chunk + 1) * 32;
#pragma unroll
            for (int i = 0; i < 2; i++) {
                int gr = m0 + a_row[i];
                pa[i] = make_uint4(0u, 0u, 0u, 0u);
                if (gr < M)
                    pa[i] = *(const uint4*)(A + (size_t)gr * K_ + k0 + a_kg * 8);
            }
            int row = tid >> 2, kg = tid & 3;
            pb = *(const uint4*)(Bw + (size_t)row * K_ + k0 + kg * 8);
        }

#pragma unroll
        for (int ks = 0; ks < 2; ks++) {
            uint32_t am[2][4];
#pragma unroll
            for (int mt = 0; mt < 2; mt++) {
                LDMATRIX_X4(am[mt], lm_addr64(sb, wm * 32 + mt * 16, ks, lane));
            }
#pragma unroll
            for (int nt = 0; nt < NT16; nt++) {
                uint32_t bm[4];
                LDMATRIX_X4(bm, lm_addr64(sb + OFF_B, wn * (N_ / 2) + nt * 16,
                                          ks, lane));
#pragma unroll
                for (int mt = 0; mt < 2; mt++) {
                    MMA_F16(acc[mt][nt * 2 + 0], am[mt], bm[0], bm[2]);
                    MMA_F16(acc[mt][nt * 2 + 1], am[mt], bm[1], bm[3]);
                }
            }
        }
        __syncthreads();
    }

#pragma unroll
    for (int mt = 0; mt < 2; mt++) {
#pragma unroll
        for (int nt8 = 0; nt8 < N_ / 16; nt8++) {
            const float* c = acc[mt][nt8];
            int row0 = m0 + wm * 32 + mt * 16 + (lane >> 2);
            int col = wn * (N_ / 2) + nt8 * 8 + 2 * (lane & 3);
            __half2 p0 = __floats2half2_rn(c[0], c[1]);
            __half2 p1 = __floats2half2_rn(c[2], c[3]);
            if (row0 < M)
                *(uint32_t*)(g_h2 + (size_t)row0 * N_ + col) = *(uint32_t*)&p0;
            if (row0 + 8 < M)
                *(uint32_t*)(g_h2 + (size_t)(row0 + 8) * N_ + col) = *(uint32_t*)&p1;
        }
    }
}

// ---------------------------------------------------------------------------
// SpMM layer 1: a1 = relu(Ahat @ h1(fp16) + b1), fp16-stored. warp/node.
// ---------------------------------------------------------------------------

__launch_bounds__(256)
__global__ void k_spmm1(const float* __restrict__ bias, int n) {
    int w = (blockIdx.x * 256 + threadIdx.x) >> 5;
    int lane = threadIdx.x & 31;
    if (w >= n) return;
    int beg = g_rowstart[w], end = g_rowstart[w + 1];

    float4 acc = make_float4(0.f, 0.f, 0.f, 0.f);
    const __half* hb = g_h1 + lane * 4;
    for (int e = beg; e < end; e++) {
        int2 cw = g_cw[e];
        float wt = __int_as_float(cw.y);
        uint2 raw = *(const uint2*)(hb + (size_t)cw.x * 128);
        float2 f01 = __half22float2(*reinterpret_cast<__half2*>(&raw.x));
        float2 f23 = __half22float2(*reinterpret_cast<__half2*>(&raw.y));
        acc.x += wt * f01.x; acc.y += wt * f01.y;
        acc.z += wt * f23.x; acc.w += wt * f23.y;
    }
    float4 b = *(const float4*)(bias + lane * 4);
    __half2 p0 = __floats2half2_rn(fmaxf(acc.x + b.x, 0.f),
                                   fmaxf(acc.y + b.y, 0.f));
    __half2 p1 = __floats2half2_rn(fmaxf(acc.z + b.z, 0.f),
                                   fmaxf(acc.w + b.w, 0.f));
    *(uint2*)(g_a1 + (size_t)w * 128 + lane * 4) =
        make_uint2(*(uint32_t*)&p0, *(uint32_t*)&p1);
}

// ---------------------------------------------------------------------------
// SpMM layer 2: out = Ahat @ h2(fp16) + b2, F=64.
// ---------------------------------------------------------------------------

__launch_bounds__(256)
__global__ void k_spmm2(const float* __restrict__ bias, float* __restrict__ out,
                        int n) {
    int w = (blockIdx.x * 256 + threadIdx.x) >> 5;
    int lane = threadIdx.x & 31;
    if (w >= n) return;
    int beg = g_rowstart[w], end = g_rowstart[w + 1];

    float2 acc = make_float2(0.f, 0.f);
    const __half* hb = g_h2 + lane * 2;
    for (int e = beg; e < end; e++) {
        int2 cw = g_cw[e];
        float wt = __int_as_float(cw.y);
        uint32_t raw = *(const uint32_t*)(hb + (size_t)cw.x * 64);
        float2 v = __half22float2(*reinterpret_cast<__half2*>(&raw));
        acc.x += wt * v.x; acc.y += wt * v.y;
    }
    float2 b = *(const float2*)(bias + lane * 2);
    acc.x += b.x; acc.y += b.y;
    *(float2*)(out + (size_t)w * 64 + lane * 2) = acc;
}

// ---------------------------------------------------------------------------

extern "C" void kernel_launch(void* const* d_in, const int* in_sizes, int n_in,
                              void* d_out, int out_size) {
    const float* x = (const float*)d_in[0];
    const int* ei = (const int*)d_in[1];      // int32
    const float* W1 = (const float*)d_in[2];
    const float* b1 = (const float*)d_in[3];
    const float* W2 = (const float*)d_in[4];
    const float* b2 = (const float*)d_in[5];
    float* out = (float*)d_out;

    const int N = in_sizes[0] / 256;   // 100000
    const int E = in_sizes[1] / 2;     // 1600000
    const int* src = ei;
    const int* dst = ei + E;
    const int NB = (N + 1023) / 1024;

    // #1..#3
    k_wcvt_init<<<(N + 255) / 256, 256>>>(W1, W2, N);
    k_count<<<(E + 255) / 256, 256>>>(dst, E);
    k_scan1<<<NB, 1024>>>(N);

    // #4: GEMM1 — ncu capture lands here
    k_hgemm1<<<(N + 127) / 128, 256>>>(x, N);

    // #5..#6: CSR finish
    k_scanfill<<<NB, 1024>>>(N, NB);
    k_fill_edges<<<(E + 255) / 256, 256>>>(src, dst, E);

    // #7: a1 = relu(Ahat h1 + b1), fp16
    k_spmm1<<<((N * 32) + 255) / 256, 256>>>(b1, N);

    // #8: h2 = a1 @ W2
    k_hgemm2<<<(N + 127) / 128, 256>>>(N);

    // #9: out = Ahat h2 + b2
    k_spmm2<<<((N * 32) + 255) / 256, 256>>>(b2, out, N);
}

// round 14
// speedup vs baseline: 1.1151x; 1.0674x over previous
#include <cuda_runtime.h>
#include <cuda_fp16.h>
#include <cstdint>
#include <cstddef>

// ---------------------------------------------------------------------------
// GCN 2-layer forward on GB300 — fp16 HMMA GEMMs + gather SpMM.
//   h1 = x @ W1           (fp16 HMMA, BM=128)              [k_hgemm1]
//   a1 = relu(Ahat h1+b1) (fp16-stored)                    [k_spmm1]
//   h2 = a1 @ W2          (fp16 HMMA, fp16 A path)         [k_hgemm2]
//   out = Ahat h2 + b2    (fp32 out)                       [k_spmm2]
// R14: CSR build (count/scan/scanfill/fill_edges) forked onto a second
// stream, overlapping with GEMM1 (independent). Event fork/join keeps the
// whole thing graph-capturable.
// ---------------------------------------------------------------------------

#define NNODES 100000
#define NEDGES 1600000
#define NNZ    (NNODES + NEDGES)

__device__ int   g_deg[NNODES];
__device__ int   g_fill[NNODES];
__device__ int   g_rowstart[NNODES + 1];
__device__ int   g_bsums[256];
__device__ float g_dinv[NNODES];
__device__ int2  g_cw[NNZ];                     // .x = col, .y = wgt bits
__device__ __half g_h1[(size_t)NNODES * 128];   // h1 (fp16)
__device__ __half g_a1[(size_t)NNODES * 128];   // a1 (fp16)
__device__ __half g_h2[(size_t)NNODES * 64];    // h2 (fp16)
// W transposed K-major [N][K], fp16
__device__ __half g_w1[128 * 256];
__device__ __half g_w2[64 * 128];

// ------------------------------ helpers ------------------------------------

__device__ __forceinline__ uint32_t smem_u32(const void* p) {
    uint32_t a;
    asm("{ .reg .u64 t; cvta.to.shared.u64 t, %1; cvt.u32.u64 %0, t; }"
        : "=r"(a) : "l"(p));
    return a;
}

#define LDMATRIX_X4(r, addr) \
    asm volatile("ldmatrix.sync.aligned.m8n8.x4.shared.b16 {%0,%1,%2,%3}, [%4];" \
                 : "=r"((r)[0]), "=r"((r)[1]), "=r"((r)[2]), "=r"((r)[3]) \
                 : "r"(addr))

#define MMA_F16(c, a, b0, b1) \
    asm volatile( \
        "mma.sync.aligned.m16n8k16.row.col.f32.f16.f16.f32 " \
        "{%0,%1,%2,%3}, {%4,%5,%6,%7}, {%8,%9}, {%0,%1,%2,%3};" \
        : "+f"((c)[0]), "+f"((c)[1]), "+f"((c)[2]), "+f"((c)[3]) \
        : "r"((a)[0]), "r"((a)[1]), "r"((a)[2]), "r"((a)[3]), \
          "r"(b0), "r"(b1))

// ldmatrix x4 address, 64B-row buffer: swizzle kg ^= (row>>1)&3
__device__ __forceinline__ uint32_t lm_addr64(uint32_t buf, int rowbase, int ks,
                                              int lane) {
    int row = rowbase + (lane & 15);
    int kg = ks * 2 + (lane >> 4);
    return buf + row * 64 + (((kg ^ ((row >> 1) & 3))) << 4);
}

// ---------------------------------------------------------------------------
// CSR construction
// ---------------------------------------------------------------------------

// W convert (both layers) + deg init, one launch
__global__ void k_wcvt_init(const float* __restrict__ W1,
                            const float* __restrict__ W2, int n) {
    int idx = blockIdx.x * blockDim.x + threadIdx.x;
    if (idx < 128 * 256) {                 // W1: K=256, N=128
        int nn = idx / 256, k = idx % 256;
        g_w1[idx] = __float2half_rn(W1[k * 128 + nn]);
    } else if (idx < 128 * 256 + 64 * 128) {  // W2: K=128, N=64
        int j = idx - 128 * 256;
        int nn = j / 128, k = j % 128;
        g_w2[j] = __float2half_rn(W2[k * 64 + nn]);
    }
    if (idx < n) g_deg[idx] = 1;           // self loop
}

__global__ void k_count(const int* __restrict__ dst, int e) {
    int i = blockIdx.x * blockDim.x + threadIdx.x;
    if (i < e) atomicAdd(&g_deg[dst[i]], 1);
}

__global__ void k_scan1(int n) {
    __shared__ int s[1024];
    int gid = blockIdx.x * 1024 + threadIdx.x;
    int v = (gid < n) ? g_deg[gid] : 0;
    s[threadIdx.x] = v;
    __syncthreads();
    for (int off = 1; off < 1024; off <<= 1) {
        int t = (threadIdx.x >= off) ? s[threadIdx.x - off] : 0;
        __syncthreads();
        s[threadIdx.x] += t;
        __syncthreads();
    }
    if (gid < n) g_rowstart[gid] = s[threadIdx.x] - v;
    if (threadIdx.x == 1023) g_bsums[blockIdx.x] = s[1023];
}

__global__ void k_scanfill(int n, int nb) {
    __shared__ int soff;
    int gid = blockIdx.x * 1024 + threadIdx.x;
    if (threadIdx.x == 0) {
        int o = 0;
        for (int b = 0; b < (int)blockIdx.x; b++) o += g_bsums[b];
        soff = o;
    }
    __syncthreads();
    if (gid < n) {
        int rs = g_rowstart[gid] + soff;
        g_rowstart[gid] = rs;
        float d = rsqrtf((float)g_deg[gid]);
        g_dinv[gid] = d;
        g_cw[rs] = make_int2(gid, __float_as_int(d * d));
        g_fill[gid] = 1;
    }
    if (gid == 0) {
        int o = 0;
        for (int b = 0; b < nb; b++) o += g_bsums[b];
        g_rowstart[n] = o;
    }
}

__global__ void k_fill_edges(const int* __restrict__ src,
                             const int* __restrict__ dst, int e) {
    int i = blockIdx.x * blockDim.x + threadIdx.x;
    if (i < e) {
        int s = src[i];
        int d = dst[i];
        int p = g_rowstart[d] + atomicAdd(&g_fill[d], 1);
        g_cw[p] = make_int2(s, __float_as_int(g_dinv[s] * g_dinv[d]));
    }
}

// ---------------------------------------------------------------------------
// GEMM1: h1[M,128] = x[M,256](fp32) @ W1, fp16 HMMA, BM=128, reg dbuf.
// ---------------------------------------------------------------------------

__global__ void __launch_bounds__(256, 2) k_hgemm1(const float* __restrict__ A,
                                                   int M) {
    constexpr int N_ = 128, K_ = 256;
    constexpr int NCHUNK = K_ / 32;
    constexpr int NT16 = N_ / 32;
    constexpr int NBQ = 2;
    constexpr int OFF_B = 8192;

    __shared__ __align__(128) char smem[8192 + N_ * 64];

    const __half* __restrict__ Bw = g_w1;
    const uint32_t sb = smem_u32(smem);
    const int tid = threadIdx.x;
    const int wid = tid >> 5, lane = tid & 31;
    const int wm = wid & 3, wn = wid >> 2;
    const int m0 = blockIdx.x * 128;

    float acc[2][N_ / 16][4];
#pragma unroll
    for (int i = 0; i < 2; i++)
#pragma unroll
        for (int j = 0; j < N_ / 16; j++)
#pragma unroll
            for (int q = 0; q < 4; q++) acc[i][j][q] = 0.f;

    const int a_row[4] = {tid >> 3, (tid + 256) >> 3, (tid + 512) >> 3,
                          (tid + 768) >> 3};
    const int a_f4 = tid & 7;

    float4 pa[4];
    uint4 pb[NBQ];
#pragma unroll
    for (int i = 0; i < 4; i++) {
        int gr = m0 + a_row[i];
        pa[i] = make_float4(0.f, 0.f, 0.f, 0.f);
        if (gr < M) pa[i] = *(const float4*)(A + (size_t)gr * K_ + a_f4 * 4);
    }
#pragma unroll
    for (int i = 0; i < NBQ; i++) {
        int idx = tid + i * 256;
        int row = idx >> 2, kg = idx & 3;
        pb[i] = *(const uint4*)(Bw + (size_t)row * K_ + kg * 8);
    }

    for (int chunk = 0; chunk < NCHUNK; chunk++) {
#pragma unroll
        for (int i = 0; i < 4; i++) {
            float4 v = pa[i];
            int row = a_row[i];
            __half2 p0 = __floats2half2_rn(v.x, v.y);
            __half2 p1 = __floats2half2_rn(v.z, v.w);
            int kg = a_f4 >> 1, half = a_f4 & 1;
            uint32_t byte = row * 64 + ((kg ^ ((row >> 1) & 3)) << 4) + half * 8;
            *(uint2*)(smem + byte) = make_uint2(*(uint32_t*)&p0, *(uint32_t*)&p1);
        }
#pragma unroll
        for (int i = 0; i < NBQ; i++) {
            int idx = tid + i * 256;
            int row = idx >> 2, kg = idx & 3;
            uint32_t byte = row * 64 + ((kg ^ ((row >> 1) & 3)) << 4);
            *(uint4*)(smem + OFF_B + byte) = pb[i];
        }
        __syncthreads();

        if (chunk + 1 < NCHUNK) {
            const int k0 = (chunk + 1) * 32;
#pragma unroll
            for (int i = 0; i < 4; i++) {
                int gr = m0 + a_row[i];
                pa[i] = make_float4(0.f, 0.f, 0.f, 0.f);
                if (gr < M)
                    pa[i] = *(const float4*)(A + (size_t)gr * K_ + k0 + a_f4 * 4);
            }
#pragma unroll
            for (int i = 0; i < NBQ; i++) {
                int idx = tid + i * 256;
                int row = idx >> 2, kg = idx & 3;
                pb[i] = *(const uint4*)(Bw + (size_t)row * K_ + k0 + kg * 8);
            }
        }

#pragma unroll
        for (int ks = 0; ks < 2; ks++) {
            uint32_t am[2][4];
#pragma unroll
            for (int mt = 0; mt < 2; mt++) {
                LDMATRIX_X4(am[mt], lm_addr64(sb, wm * 32 + mt * 16, ks, lane));
            }
#pragma unroll
            for (int nt = 0; nt < NT16; nt++) {
                uint32_t bm[4];
                LDMATRIX_X4(bm, lm_addr64(sb + OFF_B, wn * (N_ / 2) + nt * 16,
                                          ks, lane));
#pragma unroll
                for (int mt = 0; mt < 2; mt++) {
                    MMA_F16(acc[mt][nt * 2 + 0], am[mt], bm[0], bm[2]);
                    MMA_F16(acc[mt][nt * 2 + 1], am[mt], bm[1], bm[3]);
                }
            }
        }
        __syncthreads();
    }

#pragma unroll
    for (int mt = 0; mt < 2; mt++) {
#pragma unroll
        for (int nt8 = 0; nt8 < N_ / 16; nt8++) {
            const float* c = acc[mt][nt8];
            int row0 = m0 + wm * 32 + mt * 16 + (lane >> 2);
            int col = wn * (N_ / 2) + nt8 * 8 + 2 * (lane & 3);
            __half2 p0 = __floats2half2_rn(c[0], c[1]);
            __half2 p1 = __floats2half2_rn(c[2], c[3]);
            if (row0 < M)
                *(uint32_t*)(g_h1 + (size_t)row0 * N_ + col) = *(uint32_t*)&p0;
            if (row0 + 8 < M)
                *(uint32_t*)(g_h1 + (size_t)(row0 + 8) * N_ + col) = *(uint32_t*)&p1;
        }
    }
}

// ---------------------------------------------------------------------------
// GEMM2: h2[M,64] = a1[M,128](fp16) @ W2, fp16 A path.
// ---------------------------------------------------------------------------

__global__ void __launch_bounds__(256, 2) k_hgemm2(int M) {
    constexpr int N_ = 64, K_ = 128;
    constexpr int NCHUNK = K_ / 32;      // 4
    constexpr int NT16 = N_ / 32;        // 2
    constexpr int OFF_B = 8192;

    __shared__ __align__(128) char smem[8192 + N_ * 64];

    const __half* __restrict__ A = g_a1;
    const __half* __restrict__ Bw = g_w2;
    const uint32_t sb = smem_u32(smem);
    const int tid = threadIdx.x;
    const int wid = tid >> 5, lane = tid & 31;
    const int wm = wid & 3, wn = wid >> 2;
    const int m0 = blockIdx.x * 128;

    float acc[2][N_ / 16][4];
#pragma unroll
    for (int i = 0; i < 2; i++)
#pragma unroll
        for (int j = 0; j < N_ / 16; j++)
#pragma unroll
            for (int q = 0; q < 4; q++) acc[i][j][q] = 0.f;

    const int a_row[2] = {tid >> 2, (tid + 256) >> 2};
    const int a_kg = tid & 3;

    uint4 pa[2];
    uint4 pb;
#pragma unroll
    for (int i = 0; i < 2; i++) {
        int gr = m0 + a_row[i];
        pa[i] = make_uint4(0u, 0u, 0u, 0u);
        if (gr < M) pa[i] = *(const uint4*)(A + (size_t)gr * K_ + a_kg * 8);
    }
    {
        int row = tid >> 2, kg = tid & 3;
        pb = *(const uint4*)(Bw + (size_t)row * K_ + kg * 8);
    }

    for (int chunk = 0; chunk < NCHUNK; chunk++) {
#pragma unroll
        for (int i = 0; i < 2; i++) {
            int row = a_row[i];
            uint32_t byte = row * 64 + ((a_kg ^ ((row >> 1) & 3)) << 4);
            *(uint4*)(smem + byte) = pa[i];
        }
        {
            int row = tid >> 2, kg = tid & 3;
            uint32_t byte = row * 64 + ((kg ^ ((row >> 1) & 3)) << 4);
            *(uint4*)(smem + OFF_B + byte) = pb;
        }
        __syncthreads();

        if (chunk + 1 < NCHUNK) {
            const int k0 = (chunk + 1) * 32;
#pragma unroll
            for (int i = 0; i < 2; i++) {
                int gr = m0 + a_row[i];
                pa[i] = make_uint4(0u, 0u, 0u, 0u);
                if (gr < M)
                    pa[i] = *(const uint4*)(A + (size_t)gr * K_ + k0 + a_kg * 8);
            }
            int row = tid >> 2, kg = tid & 3;
            pb = *(const uint4*)(Bw + (size_t)row * K_ + k0 + kg * 8);
        }

#pragma unroll
        for (int ks = 0; ks < 2; ks++) {
            uint32_t am[2][4];
#pragma unroll
            for (int mt = 0; mt < 2; mt++) {
                LDMATRIX_X4(am[mt], lm_addr64(sb, wm * 32 + mt * 16, ks, lane));
            }
#pragma unroll
            for (int nt = 0; nt < NT16; nt++) {
                uint32_t bm[4];
                LDMATRIX_X4(bm, lm_addr64(sb + OFF_B, wn * (N_ / 2) + nt * 16,
                                          ks, lane));
#pragma unroll
                for (int mt = 0; mt < 2; mt++) {
                    MMA_F16(acc[mt][nt * 2 + 0], am[mt], bm[0], bm[2]);
                    MMA_F16(acc[mt][nt * 2 + 1], am[mt], bm[1], bm[3]);
                }
            }
        }
        __syncthreads();
    }

#pragma unroll
    for (int mt = 0; mt < 2; mt++) {
#pragma unroll
        for (int nt8 = 0; nt8 < N_ / 16; nt8++) {
            const float* c = acc[mt][nt8];
            int row0 = m0 + wm * 32 + mt * 16 + (lane >> 2);
            int col = wn * (N_ / 2) + nt8 * 8 + 2 * (lane & 3);
            __half2 p0 = __floats2half2_rn(c[0], c[1]);
            __half2 p1 = __floats2half2_rn(c[2], c[3]);
            if (row0 < M)
                *(uint32_t*)(g_h2 + (size_t)row0 * N_ + col) = *(uint32_t*)&p0;
            if (row0 + 8 < M)
                *(uint32_t*)(g_h2 + (size_t)(row0 + 8) * N_ + col) = *(uint32_t*)&p1;
        }
    }
}

// ---------------------------------------------------------------------------
// SpMM layer 1: a1 = relu(Ahat @ h1(fp16) + b1), fp16-stored. warp/node.
// ---------------------------------------------------------------------------

__launch_bounds__(256)
__global__ void k_spmm1(const float* __restrict__ bias, int n) {
    int w = (blockIdx.x * 256 + threadIdx.x) >> 5;
    int lane = threadIdx.x & 31;
    if (w >= n) return;
    int beg = g_rowstart[w], end = g_rowstart[w + 1];

    float4 acc = make_float4(0.f, 0.f, 0.f, 0.f);
    const __half* hb = g_h1 + lane * 4;
    for (int e = beg; e < end; e++) {
        int2 cw = g_cw[e];
        float wt = __int_as_float(cw.y);
        uint2 raw = *(const uint2*)(hb + (size_t)cw.x * 128);
        float2 f01 = __half22float2(*reinterpret_cast<__half2*>(&raw.x));
        float2 f23 = __half22float2(*reinterpret_cast<__half2*>(&raw.y));
        acc.x += wt * f01.x; acc.y += wt * f01.y;
        acc.z += wt * f23.x; acc.w += wt * f23.y;
    }
    float4 b = *(const float4*)(bias + lane * 4);
    __half2 p0 = __floats2half2_rn(fmaxf(acc.x + b.x, 0.f),
                                   fmaxf(acc.y + b.y, 0.f));
    __half2 p1 = __floats2half2_rn(fmaxf(acc.z + b.z, 0.f),
                                   fmaxf(acc.w + b.w, 0.f));
    *(uint2*)(g_a1 + (size_t)w * 128 + lane * 4) =
        make_uint2(*(uint32_t*)&p0, *(uint32_t*)&p1);
}

// ---------------------------------------------------------------------------
// SpMM layer 2: out = Ahat @ h2(fp16) + b2, F=64.
// ---------------------------------------------------------------------------

__launch_bounds__(256)
__global__ void k_spmm2(const float* __restrict__ bias, float* __restrict__ out,
                        int n) {
    int w = (blockIdx.x * 256 + threadIdx.x) >> 5;
    int lane = threadIdx.x & 31;
    if (w >= n) return;
    int beg = g_rowstart[w], end = g_rowstart[w + 1];

    float2 acc = make_float2(0.f, 0.f);
    const __half* hb = g_h2 + lane * 2;
    for (int e = beg; e < end; e++) {
        int2 cw = g_cw[e];
        float wt = __int_as_float(cw.y);
        uint32_t raw = *(const uint32_t*)(hb + (size_t)cw.x * 64);
        float2 v = __half22float2(*reinterpret_cast<__half2*>(&raw));
        acc.x += wt * v.x; acc.y += wt * v.y;
    }
    float2 b = *(const float2*)(bias + lane * 2);
    acc.x += b.x; acc.y += b.y;
    *(float2*)(out + (size_t)w * 64 + lane * 2) = acc;
}

// ---------------------------------------------------------------------------

extern "C" void kernel_launch(void* const* d_in, const int* in_sizes, int n_in,
                              void* d_out, int out_size) {
    const float* x = (const float*)d_in[0];
    const int* ei = (const int*)d_in[1];      // int32
    const float* W1 = (const float*)d_in[2];
    const float* b1 = (const float*)d_in[3];
    const float* W2 = (const float*)d_in[4];
    const float* b2 = (const float*)d_in[5];
    float* out = (float*)d_out;

    const int N = in_sizes[0] / 256;   // 100000
    const int E = in_sizes[1] / 2;     // 1600000
    const int* src = ei;
    const int* dst = ei + E;
    const int NB = (N + 1023) / 1024;

    // Fork a side stream for the CSR build so it overlaps with GEMM1.
    // Host-object creation only (no device allocation); not destroyed here
    // to avoid touching capture state mid-capture.
    cudaStream_t s2;
    cudaStreamCreateWithFlags(&s2, cudaStreamNonBlocking);
    cudaEvent_t evFork, evJoin;
    cudaEventCreateWithFlags(&evFork, cudaEventDisableTiming);
    cudaEventCreateWithFlags(&evJoin, cudaEventDisableTiming);

    // #1 (main): W convert + deg init — prerequisite for both branches
    k_wcvt_init<<<(N + 255) / 256, 256>>>(W1, W2, N);
    cudaEventRecord(evFork, 0);
    cudaStreamWaitEvent(s2, evFork, 0);

    // CSR branch (s2): count -> scan1 -> scanfill -> fill_edges
    k_count<<<(E + 255) / 256, 256, 0, s2>>>(dst, E);
    k_scan1<<<NB, 1024, 0, s2>>>(N);
    k_scanfill<<<NB, 1024, 0, s2>>>(N, NB);
    k_fill_edges<<<(E + 255) / 256, 256, 0, s2>>>(src, dst, E);
    cudaEventRecord(evJoin, s2);

    // GEMM branch (main): h1 = x @ W1, concurrent with CSR build
    k_hgemm1<<<(N + 127) / 128, 256>>>(x, N);

    // join: spmm1 needs both h1 and the CSR
    cudaStreamWaitEvent(0, evJoin, 0);

    // a1 = relu(Ahat h1 + b1), fp16
    k_spmm1<<<((N * 32) + 255) / 256, 256>>>(b1, N);

    // h2 = a1 @ W2
    k_hgemm2<<<(N + 127) / 128, 256>>>(N);

    // out = Ahat h2 + b2
    k_spmm2<<<((N * 32) + 255) / 256, 256>>>(b2, out, N);
}